// round 2
// baseline (speedup 1.0000x reference)
#include <cuda_runtime.h>
#include <math.h>
#include <float.h>

// Problem constants
constexpr int kB = 8;
constexpr int kS = 2048;
constexpr int kH = 768;
constexpr int kM = kB * kS;          // 16384 rows for projections
constexpr float kEPS = 1e-12f;

// ---------------------------------------------------------------------------
// Scratch (static device globals; no allocations allowed in kernel_launch)
// ---------------------------------------------------------------------------
__device__ float g_q[(size_t)kM * kH];          // 50 MB
__device__ float g_k[(size_t)kM * kH];          // 50 MB
__device__ float g_v[(size_t)kM * kH];          // 50 MB
__device__ float g_p[(size_t)kB * kS * kS];     // 134 MB  scores/probs
__device__ float g_ctx[(size_t)kM * kH];        // 50 MB
__device__ float g_h[(size_t)kM * kH];          // 50 MB   pre-LN

// ---------------------------------------------------------------------------
// fp32 SGEMM, double-buffered smem pipeline.
//   C[M,N] = A[M,K] @ B (+ epilogue)
//   TRANSB=false: B row-major [K,N];  TRANSB=true: B row-major [N,K]
//   EPI: 0 = store, 1 = +bias[n], 2 = +bias[n] + resid[m,n]
// 128x128 tile, BK=16, 256 threads, 8x8 micro-tile, blockIdx.z = batch.
// All problem dims divide the tile sizes.
// ---------------------------------------------------------------------------
constexpr int BM = 128, BN = 128, BK = 16, TM = 8, TN = 8;

template <bool TRANSB, int EPI>
__global__ __launch_bounds__(256)
void sgemm_kernel(const float* __restrict__ Ag, const float* __restrict__ Bg,
                  float* __restrict__ Cg,
                  const float* __restrict__ bias,
                  const float* __restrict__ resid,
                  int M, int N, int K,
                  size_t sA, size_t sB, size_t sC)
{
    __shared__ float As[2][BK][BM + 4];
    __shared__ float Bs[2][BK][BN + 4];

    const int z = blockIdx.z;
    const float* A  = Ag + (size_t)z * sA;
    const float* Bm = Bg + (size_t)z * sB;
    float*       C  = Cg + (size_t)z * sC;

    const int m0 = blockIdx.y * BM;
    const int n0 = blockIdx.x * BN;
    const int tid = threadIdx.x;
    const int tx = tid & 15;      // 0..15 -> N
    const int ty = tid >> 4;      // 0..15 -> M

    // ---- per-thread load coordinates (fixed across iterations) ----
    // A tile: 512 float4 loads (128 rows x 4 float4), 2 per thread
    int a_r[2], a_c4[2];
    #pragma unroll
    for (int l = 0; l < 2; l++) {
        int f = tid + l * 256;
        a_r[l]  = f >> 2;            // m row 0..127
        a_c4[l] = (f & 3) << 2;      // k col 0,4,8,12
    }
    // B tile coordinates
    int b_r[2], b_c4[2];
    #pragma unroll
    for (int l = 0; l < 2; l++) {
        int f = tid + l * 256;
        if (!TRANSB) { b_r[l] = f >> 5; b_c4[l] = (f & 31) << 2; }  // [k][n]
        else         { b_r[l] = f >> 2; b_c4[l] = (f & 3) << 2;  }  // [n][k]
    }

    auto loadA = [&](int k0, int l) -> float4 {
        return *reinterpret_cast<const float4*>(
            A + (size_t)(m0 + a_r[l]) * K + k0 + a_c4[l]);
    };
    auto loadB = [&](int k0, int l) -> float4 {
        if (!TRANSB)
            return *reinterpret_cast<const float4*>(
                Bm + (size_t)(k0 + b_r[l]) * N + n0 + b_c4[l]);
        else
            return *reinterpret_cast<const float4*>(
                Bm + (size_t)(n0 + b_r[l]) * K + k0 + b_c4[l]);
    };
    auto storeA = [&](int buf, int l, float4 v) {
        // store transposed: As[k][m]
        As[buf][a_c4[l] + 0][a_r[l]] = v.x;
        As[buf][a_c4[l] + 1][a_r[l]] = v.y;
        As[buf][a_c4[l] + 2][a_r[l]] = v.z;
        As[buf][a_c4[l] + 3][a_r[l]] = v.w;
    };
    auto storeB = [&](int buf, int l, float4 v) {
        if (!TRANSB) {
            Bs[buf][b_r[l]][b_c4[l] + 0] = v.x;
            Bs[buf][b_r[l]][b_c4[l] + 1] = v.y;
            Bs[buf][b_r[l]][b_c4[l] + 2] = v.z;
            Bs[buf][b_r[l]][b_c4[l] + 3] = v.w;
        } else {
            // transpose [n][k] -> Bs[k][n]
            Bs[buf][b_c4[l] + 0][b_r[l]] = v.x;
            Bs[buf][b_c4[l] + 1][b_r[l]] = v.y;
            Bs[buf][b_c4[l] + 2][b_r[l]] = v.z;
            Bs[buf][b_c4[l] + 3][b_r[l]] = v.w;
        }
    };

    float acc[TM][TN] = {};

    // ---- prologue: fill buffer 0
    {
        float4 a0 = loadA(0, 0), a1 = loadA(0, 1);
        float4 b0 = loadB(0, 0), b1 = loadB(0, 1);
        storeA(0, 0, a0); storeA(0, 1, a1);
        storeB(0, 0, b0); storeB(0, 1, b1);
    }
    __syncthreads();

    int cur = 0;
    for (int k0 = BK; k0 < K; k0 += BK, cur ^= 1) {
        // prefetch next slab into registers (overlaps with compute below)
        float4 a0 = loadA(k0, 0), a1 = loadA(k0, 1);
        float4 b0 = loadB(k0, 0), b1 = loadB(k0, 1);

        // compute on current buffer
        #pragma unroll
        for (int k = 0; k < BK; k++) {
            float4 A0 = *reinterpret_cast<const float4*>(&As[cur][k][ty * TM]);
            float4 A1 = *reinterpret_cast<const float4*>(&As[cur][k][ty * TM + 4]);
            float4 B0 = *reinterpret_cast<const float4*>(&Bs[cur][k][tx * TN]);
            float4 B1 = *reinterpret_cast<const float4*>(&Bs[cur][k][tx * TN + 4]);
            float a[TM] = {A0.x, A0.y, A0.z, A0.w, A1.x, A1.y, A1.z, A1.w};
            float b[TN] = {B0.x, B0.y, B0.z, B0.w, B1.x, B1.y, B1.z, B1.w};
            #pragma unroll
            for (int i = 0; i < TM; i++)
                #pragma unroll
                for (int j = 0; j < TN; j++)
                    acc[i][j] = fmaf(a[i], b[j], acc[i][j]);
        }

        // store prefetched slab into the other buffer
        storeA(cur ^ 1, 0, a0); storeA(cur ^ 1, 1, a1);
        storeB(cur ^ 1, 0, b0); storeB(cur ^ 1, 1, b1);
        __syncthreads();
    }

    // ---- last slab
    #pragma unroll
    for (int k = 0; k < BK; k++) {
        float4 A0 = *reinterpret_cast<const float4*>(&As[cur][k][ty * TM]);
        float4 A1 = *reinterpret_cast<const float4*>(&As[cur][k][ty * TM + 4]);
        float4 B0 = *reinterpret_cast<const float4*>(&Bs[cur][k][tx * TN]);
        float4 B1 = *reinterpret_cast<const float4*>(&Bs[cur][k][tx * TN + 4]);
        float a[TM] = {A0.x, A0.y, A0.z, A0.w, A1.x, A1.y, A1.z, A1.w};
        float b[TN] = {B0.x, B0.y, B0.z, B0.w, B1.x, B1.y, B1.z, B1.w};
        #pragma unroll
        for (int i = 0; i < TM; i++)
            #pragma unroll
            for (int j = 0; j < TN; j++)
                acc[i][j] = fmaf(a[i], b[j], acc[i][j]);
    }

    // ---- epilogue
    #pragma unroll
    for (int i = 0; i < TM; i++) {
        const int m = m0 + ty * TM + i;
        #pragma unroll
        for (int j = 0; j < TN; j += 4) {
            const int n = n0 + tx * TN + j;
            float4 r4;
            r4.x = acc[i][j + 0];
            r4.y = acc[i][j + 1];
            r4.z = acc[i][j + 2];
            r4.w = acc[i][j + 3];
            if (EPI >= 1) {
                float4 bi = *reinterpret_cast<const float4*>(bias + n);
                r4.x += bi.x; r4.y += bi.y; r4.z += bi.z; r4.w += bi.w;
            }
            if (EPI == 2) {
                float4 h4 = *reinterpret_cast<const float4*>(
                    resid + (size_t)m * N + n);
                r4.x += h4.x; r4.y += h4.y; r4.z += h4.z; r4.w += h4.w;
            }
            *reinterpret_cast<float4*>(C + (size_t)m * N + n) = r4;
        }
    }
}

// ---------------------------------------------------------------------------
// Masked softmax over rows of the score tensor (in place), 1/sqrt(H) fused.
// One block per (b, s) row; 256 threads x 8 elems. mask[b, t] masks KEYS.
// ---------------------------------------------------------------------------
__global__ __launch_bounds__(256)
void softmax_kernel(float* __restrict__ P, const int* __restrict__ mask)
{
    const int row = blockIdx.x;            // 0 .. B*S-1
    const int b = row >> 11;               // / 2048
    float* p = P + (size_t)row * kS;
    const int* mrow = mask + (size_t)b * kS;
    const float scale = 0.03608439182435161f;   // 1/sqrt(768)

    float v[8];
    int   kp[8];
    float mx = -FLT_MAX;
    #pragma unroll
    for (int i = 0; i < 8; i++) {
        const int t = threadIdx.x + (i << 8);
        kp[i] = mrow[t];
        v[i]  = p[t] * scale;
        if (kp[i]) mx = fmaxf(mx, v[i]);
    }
    #pragma unroll
    for (int o = 16; o; o >>= 1) mx = fmaxf(mx, __shfl_xor_sync(~0u, mx, o));
    __shared__ float redm[8];
    if ((threadIdx.x & 31) == 0) redm[threadIdx.x >> 5] = mx;
    __syncthreads();
    float bm = redm[0];
    #pragma unroll
    for (int w = 1; w < 8; w++) bm = fmaxf(bm, redm[w]);

    float sum = 0.f;
    #pragma unroll
    for (int i = 0; i < 8; i++) {
        v[i] = kp[i] ? __expf(v[i] - bm) : 0.f;
        sum += v[i];
    }
    #pragma unroll
    for (int o = 16; o; o >>= 1) sum += __shfl_xor_sync(~0u, sum, o);
    __shared__ float reds[8];
    if ((threadIdx.x & 31) == 0) reds[threadIdx.x >> 5] = sum;
    __syncthreads();
    float bs = 0.f;
    #pragma unroll
    for (int w = 0; w < 8; w++) bs += reds[w];

    const float inv = bs > 0.f ? 1.f / bs : 0.f;
    #pragma unroll
    for (int i = 0; i < 8; i++) {
        const int t = threadIdx.x + (i << 8);
        p[t] = v[i] * inv;
    }
}

// ---------------------------------------------------------------------------
// LayerNorm over last dim (768). One block per row; 256 threads x 3 elems.
// ---------------------------------------------------------------------------
__global__ __launch_bounds__(256)
void layernorm_kernel(const float* __restrict__ Hin,
                      const float* __restrict__ gamma,
                      const float* __restrict__ beta,
                      float* __restrict__ out)
{
    const int row = blockIdx.x;            // 0 .. 16383
    const float* x = Hin + (size_t)row * kH;

    float xv[3];
    float s = 0.f;
    #pragma unroll
    for (int i = 0; i < 3; i++) {
        xv[i] = x[threadIdx.x + i * 256];
        s += xv[i];
    }
    #pragma unroll
    for (int o = 16; o; o >>= 1) s += __shfl_xor_sync(~0u, s, o);
    __shared__ float red1[8];
    if ((threadIdx.x & 31) == 0) red1[threadIdx.x >> 5] = s;
    __syncthreads();
    float tot = 0.f;
    #pragma unroll
    for (int w = 0; w < 8; w++) tot += red1[w];
    const float mu = tot * (1.f / kH);

    float vs = 0.f;
    #pragma unroll
    for (int i = 0; i < 3; i++) {
        const float d = xv[i] - mu;
        vs += d * d;
    }
    #pragma unroll
    for (int o = 16; o; o >>= 1) vs += __shfl_xor_sync(~0u, vs, o);
    __shared__ float red2[8];
    if ((threadIdx.x & 31) == 0) red2[threadIdx.x >> 5] = vs;
    __syncthreads();
    float vtot = 0.f;
    #pragma unroll
    for (int w = 0; w < 8; w++) vtot += red2[w];
    const float inv = rsqrtf(vtot * (1.f / kH) + kEPS);

    #pragma unroll
    for (int i = 0; i < 3; i++) {
        const int c = threadIdx.x + i * 256;
        out[(size_t)row * kH + c] = (xv[i] - mu) * inv * gamma[c] + beta[c];
    }
}

// ---------------------------------------------------------------------------
// Launch
// ---------------------------------------------------------------------------
extern "C" void kernel_launch(void* const* d_in, const int* in_sizes, int n_in,
                              void* d_out, int out_size)
{
    const float* X     = (const float*)d_in[0];   // hidden_states [B,S,H]
    const int*   mask  = (const int*)  d_in[1];   // attention_mask [B,1,S]
    const float* Wq    = (const float*)d_in[2];
    const float* bq    = (const float*)d_in[3];
    const float* Wk    = (const float*)d_in[4];
    const float* bk    = (const float*)d_in[5];
    const float* Wv    = (const float*)d_in[6];
    const float* bv    = (const float*)d_in[7];
    const float* Wo    = (const float*)d_in[8];
    const float* bo    = (const float*)d_in[9];
    const float* gamma = (const float*)d_in[10];
    const float* beta  = (const float*)d_in[11];
    float* out = (float*)d_out;

    float *pq, *pk, *pv, *pp, *pctx, *ph;
    cudaGetSymbolAddress((void**)&pq,   g_q);
    cudaGetSymbolAddress((void**)&pk,   g_k);
    cudaGetSymbolAddress((void**)&pv,   g_v);
    cudaGetSymbolAddress((void**)&pp,   g_p);
    cudaGetSymbolAddress((void**)&pctx, g_ctx);
    cudaGetSymbolAddress((void**)&ph,   g_h);

    const dim3 thr(256);

    // 1) QKV projections: [16384,768] = X @ W + b
    {
        dim3 grid(kH / BN, kM / BM, 1);
        sgemm_kernel<false, 1><<<grid, thr>>>(X, Wq, pq, bq, nullptr,
                                              kM, kH, kH, 0, 0, 0);
        sgemm_kernel<false, 1><<<grid, thr>>>(X, Wk, pk, bk, nullptr,
                                              kM, kH, kH, 0, 0, 0);
        sgemm_kernel<false, 1><<<grid, thr>>>(X, Wv, pv, bv, nullptr,
                                              kM, kH, kH, 0, 0, 0);
    }

    // 2) scores[b] = Q[b] @ K[b]^T   (NT, per-batch)
    {
        dim3 grid(kS / BN, kS / BM, kB);
        sgemm_kernel<true, 0><<<grid, thr>>>(pq, pk, pp, nullptr, nullptr,
                                             kS, kS, kH,
                                             (size_t)kS * kH,
                                             (size_t)kS * kH,
                                             (size_t)kS * kS);
    }

    // 3) masked softmax rows (scale fused)
    softmax_kernel<<<kB * kS, thr>>>(pp, mask);

    // 4) ctx[b] = probs[b] @ V[b]   (NN, per-batch, K=2048)
    {
        dim3 grid(kH / BN, kS / BM, kB);
        sgemm_kernel<false, 0><<<grid, thr>>>(pp, pv, pctx, nullptr, nullptr,
                                              kS, kH, kS,
                                              (size_t)kS * kS,
                                              (size_t)kS * kH,
                                              (size_t)kS * kH);
    }

    // 5) h = ctx @ Wo + bo + hidden  (residual fused in epilogue)
    {
        dim3 grid(kH / BN, kM / BM, 1);
        sgemm_kernel<false, 2><<<grid, thr>>>(pctx, Wo, ph, bo, X,
                                              kM, kH, kH, 0, 0, 0);
    }

    // 6) LayerNorm -> out
    layernorm_kernel<<<kM, thr>>>(ph, gamma, beta, out);
}

// round 9
// speedup vs baseline: 1.7813x; 1.7813x over previous
#include <cuda_runtime.h>
#include <cuda_bf16.h>
#include <math.h>
#include <float.h>

using bf16 = __nv_bfloat16;

// Problem constants
constexpr int kB = 8;
constexpr int kS = 2048;
constexpr int kH = 768;
constexpr int kM = kB * kS;          // 16384
constexpr float kEPS = 1e-12f;

// ---------------------------------------------------------------------------
// Scratch (device globals; no allocation allowed)
// ---------------------------------------------------------------------------
__device__ bf16 g_xhi[(size_t)kM * kH];
__device__ bf16 g_xlo[(size_t)kM * kH];
__device__ bf16 g_wqth[(size_t)kH * kH], g_wqtl[(size_t)kH * kH];
__device__ bf16 g_wkth[(size_t)kH * kH], g_wktl[(size_t)kH * kH];
__device__ bf16 g_wvth[(size_t)kH * kH], g_wvtl[(size_t)kH * kH];
__device__ bf16 g_woth[(size_t)kH * kH], g_wotl[(size_t)kH * kH];
__device__ bf16 g_qhi[(size_t)kM * kH], g_qlo[(size_t)kM * kH];
__device__ bf16 g_khi[(size_t)kM * kH], g_klo[(size_t)kM * kH];
__device__ bf16 g_vhi[(size_t)kM * kH], g_vlo[(size_t)kM * kH];
__device__ bf16 g_vthi[(size_t)kM * kH], g_vtlo[(size_t)kM * kH];  // [b][h][t]
__device__ float g_p[(size_t)kB * kS * kS];
__device__ bf16 g_phi[(size_t)kB * kS * kS], g_plo[(size_t)kB * kS * kS];
__device__ bf16 g_chi[(size_t)kM * kH], g_clo[(size_t)kM * kH];    // ctx
__device__ float g_h[(size_t)kM * kH];

// ---------------------------------------------------------------------------
// helpers
// ---------------------------------------------------------------------------
__device__ __forceinline__ void split2(float v0, float v1, bf16* hi, bf16* lo,
                                       size_t off)
{
    __nv_bfloat162 hp, lp;
    hp.x = __float2bfloat16(v0);
    hp.y = __float2bfloat16(v1);
    lp.x = __float2bfloat16(v0 - __bfloat162float(hp.x));
    lp.y = __float2bfloat16(v1 - __bfloat162float(hp.y));
    *reinterpret_cast<__nv_bfloat162*>(hi + off) = hp;
    *reinterpret_cast<__nv_bfloat162*>(lo + off) = lp;
}

__device__ __forceinline__ void mma16816(float& d0, float& d1, float& d2, float& d3,
                                         unsigned a0, unsigned a1, unsigned a2, unsigned a3,
                                         unsigned b0, unsigned b1)
{
    asm volatile(
        "mma.sync.aligned.m16n8k16.row.col.f32.bf16.bf16.f32 "
        "{%0,%1,%2,%3}, {%4,%5,%6,%7}, {%8,%9}, {%0,%1,%2,%3};"
        : "+f"(d0), "+f"(d1), "+f"(d2), "+f"(d3)
        : "r"(a0), "r"(a1), "r"(a2), "r"(a3), "r"(b0), "r"(b1));
}

__device__ __forceinline__ void cp16(unsigned dst, const void* src)
{
    asm volatile("cp.async.cg.shared.global [%0], [%1], 16;"
                 :: "r"(dst), "l"(src));
}
__device__ __forceinline__ void cp_commit()
{
    asm volatile("cp.async.commit_group;");
}
template <int N>
__device__ __forceinline__ void cp_wait()
{
    asm volatile("cp.async.wait_group %0;" :: "n"(N));
}

// ---------------------------------------------------------------------------
// bf16-split tensor-core GEMM:  C = A[m,k] * B[n,k]^T  over K' = 3K
//   segment 0: Ahi*Bhi, 1: Alo*Bhi, 2: Ahi*Blo   (fp32 accumulate)
// 128x128 tile, BK=32 bf16, 256 thr, warp 32x64, mma m16n8k16.
// cp.async double-buffered mainloop.
// EPI: 0 = fp32 store; 1 = split bf16 store (+bias if != null);
//      2 = fp32 + bias + resid.
// ---------------------------------------------------------------------------
constexpr int GBM = 128, GBN = 128, GBK = 32;
constexpr int ROWU = 20;   // padded row stride in uints (32 bf16 + 8 pad = 80B)

template <int EPI>
__global__ __launch_bounds__(256, 2)
void mma_gemm(const bf16* __restrict__ Ahi, const bf16* __restrict__ Alo,
              const bf16* __restrict__ Bhi, const bf16* __restrict__ Blo,
              float* __restrict__ Cf, bf16* __restrict__ Chi, bf16* __restrict__ Clo,
              const float* __restrict__ bias, const float* __restrict__ resid,
              int M, int N, int K,
              size_t sA, size_t sB, size_t sC)
{
    __shared__ unsigned sm[2][2][GBM * ROWU];   // [buf][A=0/B=1]

    const int z = blockIdx.z;
    const bf16* Azhi = Ahi + (size_t)z * sA;
    const bf16* Azlo = Alo + (size_t)z * sA;
    const bf16* Bzhi = Bhi + (size_t)z * sB;
    const bf16* Bzlo = Blo + (size_t)z * sB;

    const int m0 = blockIdx.y * GBM;
    const int n0 = blockIdx.x * GBN;
    const int tid = threadIdx.x;
    const int lane = tid & 31;
    const int warp = tid >> 5;
    const int wm = warp >> 1;          // 0..3 -> m offset wm*32
    const int wn = warp & 1;           // 0..1 -> n offset wn*64
    const int r = lane >> 2;
    const int q = lane & 3;

    // global loader coords: 512 uint4 chunks per tile, 2 per thread
    const int lr = tid >> 2;           // rows lr and lr+64
    const int lc = tid & 3;            // 16B chunk (8 bf16)

    const int kslabs = K / GBK;
    const int iters = 3 * kslabs;

    float acc[2][8][4];
    #pragma unroll
    for (int mi = 0; mi < 2; mi++)
        #pragma unroll
        for (int ni = 0; ni < 8; ni++)
            #pragma unroll
            for (int c = 0; c < 4; c++) acc[mi][ni][c] = 0.f;

    auto gsel = [&](int it, const bf16*& Ap, const bf16*& Bp, int& k0) {
        int seg = it / kslabs;
        k0 = (it - seg * kslabs) * GBK;
        Ap = (seg == 1) ? Azlo : Azhi;
        Bp = (seg == 2) ? Bzlo : Bzhi;
    };

    // per-thread smem destination byte offsets within a [A|B] buffer pair
    const unsigned dA0 = (unsigned)__cvta_generic_to_shared(
        &sm[0][0][lr * ROWU + lc * 4]);
    const unsigned dA1 = (unsigned)__cvta_generic_to_shared(
        &sm[0][0][(lr + 64) * ROWU + lc * 4]);
    const unsigned dB0 = (unsigned)__cvta_generic_to_shared(
        &sm[0][1][lr * ROWU + lc * 4]);
    const unsigned dB1 = (unsigned)__cvta_generic_to_shared(
        &sm[0][1][(lr + 64) * ROWU + lc * 4]);
    const unsigned bufStride =
        (unsigned)(sizeof(unsigned) * 2 * GBM * ROWU);   // bytes per buf

    auto issue = [&](int it, int buf) {
        const bf16 *Ap, *Bp; int k0;
        gsel(it, Ap, Bp, k0);
        const unsigned off = buf * bufStride;
        cp16(dA0 + off, Ap + (size_t)(m0 + lr) * K + k0 + lc * 8);
        cp16(dA1 + off, Ap + (size_t)(m0 + lr + 64) * K + k0 + lc * 8);
        cp16(dB0 + off, Bp + (size_t)(n0 + lr) * K + k0 + lc * 8);
        cp16(dB1 + off, Bp + (size_t)(n0 + lr + 64) * K + k0 + lc * 8);
        cp_commit();
    };

    auto compute = [&](const unsigned* __restrict__ As,
                       const unsigned* __restrict__ Bs) {
        #pragma unroll
        for (int kk = 0; kk < 2; kk++) {
            const int kc = kk * 8 + q;
            unsigned a[2][4];
            #pragma unroll
            for (int mi = 0; mi < 2; mi++) {
                const int mb = wm * 32 + mi * 16;
                a[mi][0] = As[(mb + r) * ROWU + kc];
                a[mi][1] = As[(mb + r + 8) * ROWU + kc];
                a[mi][2] = As[(mb + r) * ROWU + kc + 4];
                a[mi][3] = As[(mb + r + 8) * ROWU + kc + 4];
            }
            #pragma unroll
            for (int nh = 0; nh < 2; nh++) {
                unsigned b[4][2];
                #pragma unroll
                for (int nj = 0; nj < 4; nj++) {
                    const int nb = wn * 64 + (nh * 4 + nj) * 8;
                    b[nj][0] = Bs[(nb + r) * ROWU + kc];
                    b[nj][1] = Bs[(nb + r) * ROWU + kc + 4];
                }
                #pragma unroll
                for (int mi = 0; mi < 2; mi++)
                    #pragma unroll
                    for (int nj = 0; nj < 4; nj++) {
                        float* d = acc[mi][nh * 4 + nj];
                        mma16816(d[0], d[1], d[2], d[3],
                                 a[mi][0], a[mi][1], a[mi][2], a[mi][3],
                                 b[nj][0], b[nj][1]);
                    }
            }
        }
    };

    // prologue: slab 0 -> buffer 0
    issue(0, 0);

    for (int it = 1; it < iters; ++it) {
        cp_wait<0>();          // slab it-1 landed
        __syncthreads();       // ...and visible to all; prior compute drained
        issue(it, it & 1);     // prefetch next slab into the other buffer
        compute(sm[(it - 1) & 1][0], sm[(it - 1) & 1][1]);
    }
    cp_wait<0>();
    __syncthreads();
    compute(sm[(iters - 1) & 1][0], sm[(iters - 1) & 1][1]);

    // epilogue
    const size_t zc = (size_t)z * sC;
    #pragma unroll
    for (int mi = 0; mi < 2; mi++) {
        #pragma unroll
        for (int ni = 0; ni < 8; ni++) {
            const int row0 = m0 + wm * 32 + mi * 16 + r;
            const int col  = n0 + wn * 64 + ni * 8 + 2 * q;
            float v0 = acc[mi][ni][0], v1 = acc[mi][ni][1];
            float v2 = acc[mi][ni][2], v3 = acc[mi][ni][3];
            if (EPI == 1 && bias) {
                v0 += bias[col]; v1 += bias[col + 1];
                v2 += bias[col]; v3 += bias[col + 1];
            }
            if (EPI == 2) {
                float b0 = bias[col], b1 = bias[col + 1];
                v0 += b0 + resid[(size_t)row0 * N + col];
                v1 += b1 + resid[(size_t)row0 * N + col + 1];
                v2 += b0 + resid[(size_t)(row0 + 8) * N + col];
                v3 += b1 + resid[(size_t)(row0 + 8) * N + col + 1];
            }
            if (EPI == 0 || EPI == 2) {
                float2 p0 = {v0, v1}, p1 = {v2, v3};
                *(float2*)(Cf + zc + (size_t)row0 * N + col) = p0;
                *(float2*)(Cf + zc + (size_t)(row0 + 8) * N + col) = p1;
            } else {
                split2(v0, v1, Chi, Clo, zc + (size_t)row0 * N + col);
                split2(v2, v3, Chi, Clo, zc + (size_t)(row0 + 8) * N + col);
            }
        }
    }
}

// ---------------------------------------------------------------------------
// fp32 -> bf16 hi/lo elementwise split (x4 vectorized)
// ---------------------------------------------------------------------------
__global__ __launch_bounds__(256)
void split_kernel(const float* __restrict__ x, bf16* __restrict__ hi,
                  bf16* __restrict__ lo, int n4)
{
    int i = blockIdx.x * 256 + threadIdx.x;
    if (i >= n4) return;
    float4 v = *(const float4*)(x + (size_t)i * 4);
    split2(v.x, v.y, hi, lo, (size_t)i * 4);
    split2(v.z, v.w, hi, lo, (size_t)i * 4 + 2);
}

// ---------------------------------------------------------------------------
// W [k][n] fp32  ->  WT hi/lo [n][k] bf16   (768x768)
// ---------------------------------------------------------------------------
__global__ __launch_bounds__(256)
void wsplit_kernel(const float* __restrict__ W, bf16* __restrict__ hi,
                   bf16* __restrict__ lo)
{
    __shared__ float t[32][33];
    const int x = threadIdx.x, y = threadIdx.y;
    const int k0 = blockIdx.y * 32, n0 = blockIdx.x * 32;
    #pragma unroll
    for (int i = 0; i < 4; i++)
        t[y + i * 8][x] = W[(size_t)(k0 + y + i * 8) * kH + n0 + x];
    __syncthreads();
    #pragma unroll
    for (int i = 0; i < 4; i++) {
        float v = t[x][y + i * 8];
        bf16 h = __float2bfloat16(v);
        size_t off = (size_t)(n0 + y + i * 8) * kH + k0 + x;
        hi[off] = h;
        lo[off] = __float2bfloat16(v - __bfloat162float(h));
    }
}

// ---------------------------------------------------------------------------
// V hi/lo [b*2048+t][768]  ->  Vt hi/lo [b][768][2048]
// ---------------------------------------------------------------------------
__global__ __launch_bounds__(256)
void vtrans_kernel(const bf16* __restrict__ vh, const bf16* __restrict__ vl,
                   bf16* __restrict__ oth, bf16* __restrict__ otl)
{
    __shared__ bf16 th[32][33];
    __shared__ bf16 tl[32][33];
    const int x = threadIdx.x, y = threadIdx.y;
    const int t0 = blockIdx.x * 32, h0 = blockIdx.y * 32, z = blockIdx.z;
    #pragma unroll
    for (int i = 0; i < 4; i++) {
        size_t off = (size_t)(z * kS + t0 + y + i * 8) * kH + h0 + x;
        th[y + i * 8][x] = vh[off];
        tl[y + i * 8][x] = vl[off];
    }
    __syncthreads();
    #pragma unroll
    for (int i = 0; i < 4; i++) {
        size_t off = (size_t)z * kH * kS + (size_t)(h0 + y + i * 8) * kS + t0 + x;
        oth[off] = th[x][y + i * 8];
        otl[off] = tl[x][y + i * 8];
    }
}

// ---------------------------------------------------------------------------
// Masked softmax: reads fp32 scores, writes bf16 hi/lo probs. scale fused.
// ---------------------------------------------------------------------------
__global__ __launch_bounds__(256)
void softmax_kernel(const float* __restrict__ P, const int* __restrict__ mask,
                    bf16* __restrict__ phi, bf16* __restrict__ plo)
{
    const int row = blockIdx.x;
    const int b = row >> 11;
    const float* p = P + (size_t)row * kS;
    const int* mrow = mask + (size_t)b * kS;
    const float scale = 0.03608439182435161f;   // 1/sqrt(768)

    float v[8];
    int kp[8];
    float mx = -FLT_MAX;
    #pragma unroll
    for (int i = 0; i < 8; i++) {
        const int t = threadIdx.x + (i << 8);
        kp[i] = mrow[t];
        v[i] = p[t] * scale;
        if (kp[i]) mx = fmaxf(mx, v[i]);
    }
    #pragma unroll
    for (int o = 16; o; o >>= 1) mx = fmaxf(mx, __shfl_xor_sync(~0u, mx, o));
    __shared__ float redm[8];
    if ((threadIdx.x & 31) == 0) redm[threadIdx.x >> 5] = mx;
    __syncthreads();
    float bm = redm[0];
    #pragma unroll
    for (int w = 1; w < 8; w++) bm = fmaxf(bm, redm[w]);

    float sum = 0.f;
    #pragma unroll
    for (int i = 0; i < 8; i++) {
        v[i] = kp[i] ? __expf(v[i] - bm) : 0.f;
        sum += v[i];
    }
    #pragma unroll
    for (int o = 16; o; o >>= 1) sum += __shfl_xor_sync(~0u, sum, o);
    __shared__ float reds[8];
    if ((threadIdx.x & 31) == 0) reds[threadIdx.x >> 5] = sum;
    __syncthreads();
    float bs = 0.f;
    #pragma unroll
    for (int w = 0; w < 8; w++) bs += reds[w];

    const float inv = bs > 0.f ? 1.f / bs : 0.f;
    #pragma unroll
    for (int i = 0; i < 8; i++) {
        const int t = threadIdx.x + (i << 8);
        float pr = v[i] * inv;
        bf16 h = __float2bfloat16(pr);
        size_t off = (size_t)row * kS + t;
        phi[off] = h;
        plo[off] = __float2bfloat16(pr - __bfloat162float(h));
    }
}

// ---------------------------------------------------------------------------
// LayerNorm over last dim (768)
// ---------------------------------------------------------------------------
__global__ __launch_bounds__(256)
void layernorm_kernel(const float* __restrict__ Hin,
                      const float* __restrict__ gamma,
                      const float* __restrict__ beta,
                      float* __restrict__ out)
{
    const int row = blockIdx.x;
    const float* x = Hin + (size_t)row * kH;

    float xv[3];
    float s = 0.f;
    #pragma unroll
    for (int i = 0; i < 3; i++) {
        xv[i] = x[threadIdx.x + i * 256];
        s += xv[i];
    }
    #pragma unroll
    for (int o = 16; o; o >>= 1) s += __shfl_xor_sync(~0u, s, o);
    __shared__ float red1[8];
    if ((threadIdx.x & 31) == 0) red1[threadIdx.x >> 5] = s;
    __syncthreads();
    float tot = 0.f;
    #pragma unroll
    for (int w = 0; w < 8; w++) tot += red1[w];
    const float mu = tot * (1.f / kH);

    float vs = 0.f;
    #pragma unroll
    for (int i = 0; i < 3; i++) {
        const float d = xv[i] - mu;
        vs += d * d;
    }
    #pragma unroll
    for (int o = 16; o; o >>= 1) vs += __shfl_xor_sync(~0u, vs, o);
    __shared__ float red2[8];
    if ((threadIdx.x & 31) == 0) red2[threadIdx.x >> 5] = vs;
    __syncthreads();
    float vtot = 0.f;
    #pragma unroll
    for (int w = 0; w < 8; w++) vtot += red2[w];
    const float inv = rsqrtf(vtot * (1.f / kH) + kEPS);

    #pragma unroll
    for (int i = 0; i < 3; i++) {
        const int c = threadIdx.x + i * 256;
        out[(size_t)row * kH + c] = (xv[i] - mu) * inv * gamma[c] + beta[c];
    }
}

// ---------------------------------------------------------------------------
// Launch
// ---------------------------------------------------------------------------
extern "C" void kernel_launch(void* const* d_in, const int* in_sizes, int n_in,
                              void* d_out, int out_size)
{
    const float* X     = (const float*)d_in[0];
    const int*   mask  = (const int*)  d_in[1];
    const float* Wq    = (const float*)d_in[2];
    const float* bq    = (const float*)d_in[3];
    const float* Wk    = (const float*)d_in[4];
    const float* bk    = (const float*)d_in[5];
    const float* Wv    = (const float*)d_in[6];
    const float* bv    = (const float*)d_in[7];
    const float* Wo    = (const float*)d_in[8];
    const float* bo    = (const float*)d_in[9];
    const float* gamma = (const float*)d_in[10];
    const float* beta  = (const float*)d_in[11];
    float* out = (float*)d_out;

    bf16 *xhi, *xlo, *wqth, *wqtl, *wkth, *wktl, *wvth, *wvtl, *woth, *wotl;
    bf16 *qhi, *qlo, *khi, *klo, *vhi, *vlo, *vthi, *vtlo;
    bf16 *phi, *plo, *chi, *clo;
    float *pp, *ph;
    cudaGetSymbolAddress((void**)&xhi, g_xhi);   cudaGetSymbolAddress((void**)&xlo, g_xlo);
    cudaGetSymbolAddress((void**)&wqth, g_wqth); cudaGetSymbolAddress((void**)&wqtl, g_wqtl);
    cudaGetSymbolAddress((void**)&wkth, g_wkth); cudaGetSymbolAddress((void**)&wktl, g_wktl);
    cudaGetSymbolAddress((void**)&wvth, g_wvth); cudaGetSymbolAddress((void**)&wvtl, g_wvtl);
    cudaGetSymbolAddress((void**)&woth, g_woth); cudaGetSymbolAddress((void**)&wotl, g_wotl);
    cudaGetSymbolAddress((void**)&qhi, g_qhi);   cudaGetSymbolAddress((void**)&qlo, g_qlo);
    cudaGetSymbolAddress((void**)&khi, g_khi);   cudaGetSymbolAddress((void**)&klo, g_klo);
    cudaGetSymbolAddress((void**)&vhi, g_vhi);   cudaGetSymbolAddress((void**)&vlo, g_vlo);
    cudaGetSymbolAddress((void**)&vthi, g_vthi); cudaGetSymbolAddress((void**)&vtlo, g_vtlo);
    cudaGetSymbolAddress((void**)&phi, g_phi);   cudaGetSymbolAddress((void**)&plo, g_plo);
    cudaGetSymbolAddress((void**)&chi, g_chi);   cudaGetSymbolAddress((void**)&clo, g_clo);
    cudaGetSymbolAddress((void**)&pp, g_p);      cudaGetSymbolAddress((void**)&ph, g_h);

    const dim3 thr(256);

    // 0) operand preparation
    {
        int n4 = kM * kH / 4;
        split_kernel<<<(n4 + 255) / 256, thr>>>(X, xhi, xlo, n4);
        dim3 wg(kH / 32, kH / 32);
        dim3 wb(32, 8);
        wsplit_kernel<<<wg, wb>>>(Wq, wqth, wqtl);
        wsplit_kernel<<<wg, wb>>>(Wk, wkth, wktl);
        wsplit_kernel<<<wg, wb>>>(Wv, wvth, wvtl);
        wsplit_kernel<<<wg, wb>>>(Wo, woth, wotl);
    }

    // 1) QKV projections -> split bf16 outputs
    {
        dim3 grid(kH / GBN, kM / GBM, 1);
        mma_gemm<1><<<grid, thr>>>(xhi, xlo, wqth, wqtl, nullptr, qhi, qlo,
                                   bq, nullptr, kM, kH, kH, 0, 0, 0);
        mma_gemm<1><<<grid, thr>>>(xhi, xlo, wkth, wktl, nullptr, khi, klo,
                                   bk, nullptr, kM, kH, kH, 0, 0, 0);
        mma_gemm<1><<<grid, thr>>>(xhi, xlo, wvth, wvtl, nullptr, vhi, vlo,
                                   bv, nullptr, kM, kH, kH, 0, 0, 0);
    }

    // 1b) transpose V -> [b][h][t]
    {
        dim3 g(kS / 32, kH / 32, kB);
        dim3 b(32, 8);
        vtrans_kernel<<<g, b>>>(vhi, vlo, vthi, vtlo);
    }

    // 2) scores[b] = Q[b] @ K[b]^T  (fp32 out)
    {
        dim3 grid(kS / GBN, kS / GBM, kB);
        mma_gemm<0><<<grid, thr>>>(qhi, qlo, khi, klo, pp, nullptr, nullptr,
                                   nullptr, nullptr, kS, kS, kH,
                                   (size_t)kS * kH, (size_t)kS * kH,
                                   (size_t)kS * kS);
    }

    // 3) masked softmax -> split probs
    softmax_kernel<<<kB * kS, thr>>>(pp, mask, phi, plo);

    // 4) ctx[b] = P[b] @ V[b]  (B = Vt [h][t], split out)
    {
        dim3 grid(kH / GBN, kS / GBM, kB);
        mma_gemm<1><<<grid, thr>>>(phi, plo, vthi, vtlo, nullptr, chi, clo,
                                   nullptr, nullptr, kS, kH, kS,
                                   (size_t)kS * kS, (size_t)kH * kS,
                                   (size_t)kS * kH);
    }

    // 5) h = ctx @ Wo^T(pre-transposed) + bo + X
    {
        dim3 grid(kH / GBN, kM / GBM, 1);
        mma_gemm<2><<<grid, thr>>>(chi, clo, woth, wotl, ph, nullptr, nullptr,
                                   bo, X, kM, kH, kH, 0, 0, 0);
    }

    // 6) LayerNorm -> out
    layernorm_kernel<<<kM, thr>>>(ph, gamma, beta, out);
}

// round 13
// speedup vs baseline: 1.8603x; 1.0444x over previous
#include <cuda_runtime.h>
#include <cuda_bf16.h>
#include <math.h>
#include <float.h>

using bf16 = __nv_bfloat16;

// Problem constants
constexpr int kB = 8;
constexpr int kS = 2048;
constexpr int kH = 768;
constexpr int kM = kB * kS;          // 16384
constexpr float kEPS = 1e-12f;

// ---------------------------------------------------------------------------
// Scratch (device globals; no allocation allowed)
// ---------------------------------------------------------------------------
__device__ bf16 g_xhi[(size_t)kM * kH];
__device__ bf16 g_xlo[(size_t)kM * kH];
__device__ bf16 g_wqkvth[(size_t)3 * kH * kH], g_wqkvtl[(size_t)3 * kH * kH];
__device__ bf16 g_woth[(size_t)kH * kH], g_wotl[(size_t)kH * kH];
__device__ bf16 g_qhi[(size_t)kM * kH], g_qlo[(size_t)kM * kH];
__device__ bf16 g_khi[(size_t)kM * kH], g_klo[(size_t)kM * kH];
__device__ bf16 g_vhi[(size_t)kM * kH], g_vlo[(size_t)kM * kH];
__device__ bf16 g_vthi[(size_t)kM * kH], g_vtlo[(size_t)kM * kH];  // [b][h][t]
__device__ float g_p[(size_t)kB * kS * kS];
__device__ bf16 g_phi[(size_t)kB * kS * kS], g_plo[(size_t)kB * kS * kS];
__device__ bf16 g_chi[(size_t)kM * kH], g_clo[(size_t)kM * kH];    // ctx
__device__ float g_h[(size_t)kM * kH];

// ---------------------------------------------------------------------------
// helpers
// ---------------------------------------------------------------------------
__device__ __forceinline__ void split2(float v0, float v1, bf16* hi, bf16* lo,
                                       size_t off)
{
    __nv_bfloat162 hp, lp;
    hp.x = __float2bfloat16(v0);
    hp.y = __float2bfloat16(v1);
    lp.x = __float2bfloat16(v0 - __bfloat162float(hp.x));
    lp.y = __float2bfloat16(v1 - __bfloat162float(hp.y));
    *reinterpret_cast<__nv_bfloat162*>(hi + off) = hp;
    *reinterpret_cast<__nv_bfloat162*>(lo + off) = lp;
}

__device__ __forceinline__ void mma16816(float& d0, float& d1, float& d2, float& d3,
                                         unsigned a0, unsigned a1, unsigned a2, unsigned a3,
                                         unsigned b0, unsigned b1)
{
    asm volatile(
        "mma.sync.aligned.m16n8k16.row.col.f32.bf16.bf16.f32 "
        "{%0,%1,%2,%3}, {%4,%5,%6,%7}, {%8,%9}, {%0,%1,%2,%3};"
        : "+f"(d0), "+f"(d1), "+f"(d2), "+f"(d3)
        : "r"(a0), "r"(a1), "r"(a2), "r"(a3), "r"(b0), "r"(b1));
}

__device__ __forceinline__ void cp16(unsigned dst, const void* src)
{
    asm volatile("cp.async.cg.shared.global [%0], [%1], 16;"
                 :: "r"(dst), "l"(src));
}
__device__ __forceinline__ void cp_commit()
{
    asm volatile("cp.async.commit_group;");
}
template <int N>
__device__ __forceinline__ void cp_wait()
{
    asm volatile("cp.async.wait_group %0;" :: "n"(N));
}

// ---------------------------------------------------------------------------
// bf16-split tensor-core GEMM:  C = A[m,k] * B[n,k]^T  over K' = 3K
//   segment 0: Ahi*Bhi, 1: Alo*Bhi, 2: Ahi*Blo   (fp32 accumulate)
// 128x128 tile, BK=32 bf16, 256 thr, warp 32x64, mma m16n8k16.
// cp.async double-buffered mainloop.
// EPI: 0 = fp32 store; 1 = split bf16 store (+bias if != null);
//      2 = fp32 + bias + resid;
//      3 = merged-QKV split store: N covers [Wq|Wk|Wv] bands of width kH;
//          per-block band select of (Chi,Clo,bias) / (Khi,Klo,bias2) /
//          (Vhi,Vlo,bias3), row stride kH.
// ---------------------------------------------------------------------------
constexpr int GBM = 128, GBN = 128, GBK = 32;
constexpr int ROWU = 20;   // padded row stride in uints (32 bf16 + 8 pad = 80B)

template <int EPI>
__global__ __launch_bounds__(256, 2)
void mma_gemm(const bf16* __restrict__ Ahi, const bf16* __restrict__ Alo,
              const bf16* __restrict__ Bhi, const bf16* __restrict__ Blo,
              float* __restrict__ Cf, bf16* __restrict__ Chi, bf16* __restrict__ Clo,
              const float* __restrict__ bias, const float* __restrict__ resid,
              int M, int N, int K,
              size_t sA, size_t sB, size_t sC,
              bf16* __restrict__ Khi = nullptr, bf16* __restrict__ Klo = nullptr,
              bf16* __restrict__ Vhi = nullptr, bf16* __restrict__ Vlo = nullptr,
              const float* __restrict__ bias2 = nullptr,
              const float* __restrict__ bias3 = nullptr)
{
    __shared__ unsigned sm[2][2][GBM * ROWU];   // [buf][A=0/B=1]

    const int z = blockIdx.z;
    const bf16* Azhi = Ahi + (size_t)z * sA;
    const bf16* Azlo = Alo + (size_t)z * sA;
    const bf16* Bzhi = Bhi + (size_t)z * sB;
    const bf16* Bzlo = Blo + (size_t)z * sB;

    const int m0 = blockIdx.y * GBM;
    const int n0 = blockIdx.x * GBN;
    const int tid = threadIdx.x;
    const int lane = tid & 31;
    const int warp = tid >> 5;
    const int wm = warp >> 1;          // 0..3 -> m offset wm*32
    const int wn = warp & 1;           // 0..1 -> n offset wn*64
    const int r = lane >> 2;
    const int q = lane & 3;

    // global loader coords: 512 uint4 chunks per tile, 2 per thread
    const int lr = tid >> 2;           // rows lr and lr+64
    const int lc = tid & 3;            // 16B chunk (8 bf16)

    const int kslabs = K / GBK;
    const int iters = 3 * kslabs;

    float acc[2][8][4];
    #pragma unroll
    for (int mi = 0; mi < 2; mi++)
        #pragma unroll
        for (int ni = 0; ni < 8; ni++)
            #pragma unroll
            for (int c = 0; c < 4; c++) acc[mi][ni][c] = 0.f;

    auto gsel = [&](int it, const bf16*& Ap, const bf16*& Bp, int& k0) {
        int seg = it / kslabs;
        k0 = (it - seg * kslabs) * GBK;
        Ap = (seg == 1) ? Azlo : Azhi;
        Bp = (seg == 2) ? Bzlo : Bzhi;
    };

    // per-thread smem destination byte offsets within a [A|B] buffer pair
    const unsigned dA0 = (unsigned)__cvta_generic_to_shared(
        &sm[0][0][lr * ROWU + lc * 4]);
    const unsigned dA1 = (unsigned)__cvta_generic_to_shared(
        &sm[0][0][(lr + 64) * ROWU + lc * 4]);
    const unsigned dB0 = (unsigned)__cvta_generic_to_shared(
        &sm[0][1][lr * ROWU + lc * 4]);
    const unsigned dB1 = (unsigned)__cvta_generic_to_shared(
        &sm[0][1][(lr + 64) * ROWU + lc * 4]);
    const unsigned bufStride =
        (unsigned)(sizeof(unsigned) * 2 * GBM * ROWU);   // bytes per buf

    auto issue = [&](int it, int buf) {
        const bf16 *Ap, *Bp; int k0;
        gsel(it, Ap, Bp, k0);
        const unsigned off = buf * bufStride;
        cp16(dA0 + off, Ap + (size_t)(m0 + lr) * K + k0 + lc * 8);
        cp16(dA1 + off, Ap + (size_t)(m0 + lr + 64) * K + k0 + lc * 8);
        cp16(dB0 + off, Bp + (size_t)(n0 + lr) * K + k0 + lc * 8);
        cp16(dB1 + off, Bp + (size_t)(n0 + lr + 64) * K + k0 + lc * 8);
        cp_commit();
    };

    auto compute = [&](const unsigned* __restrict__ As,
                       const unsigned* __restrict__ Bs) {
        #pragma unroll
        for (int kk = 0; kk < 2; kk++) {
            const int kc = kk * 8 + q;
            unsigned a[2][4];
            #pragma unroll
            for (int mi = 0; mi < 2; mi++) {
                const int mb = wm * 32 + mi * 16;
                a[mi][0] = As[(mb + r) * ROWU + kc];
                a[mi][1] = As[(mb + r + 8) * ROWU + kc];
                a[mi][2] = As[(mb + r) * ROWU + kc + 4];
                a[mi][3] = As[(mb + r + 8) * ROWU + kc + 4];
            }
            #pragma unroll
            for (int nh = 0; nh < 2; nh++) {
                unsigned b[4][2];
                #pragma unroll
                for (int nj = 0; nj < 4; nj++) {
                    const int nb = wn * 64 + (nh * 4 + nj) * 8;
                    b[nj][0] = Bs[(nb + r) * ROWU + kc];
                    b[nj][1] = Bs[(nb + r) * ROWU + kc + 4];
                }
                #pragma unroll
                for (int mi = 0; mi < 2; mi++)
                    #pragma unroll
                    for (int nj = 0; nj < 4; nj++) {
                        float* d = acc[mi][nh * 4 + nj];
                        mma16816(d[0], d[1], d[2], d[3],
                                 a[mi][0], a[mi][1], a[mi][2], a[mi][3],
                                 b[nj][0], b[nj][1]);
                    }
            }
        }
    };

    // prologue: slab 0 -> buffer 0
    issue(0, 0);

    for (int it = 1; it < iters; ++it) {
        cp_wait<0>();          // slab it-1 landed
        __syncthreads();       // ...and visible to all; prior compute drained
        issue(it, it & 1);     // prefetch next slab into the other buffer
        compute(sm[(it - 1) & 1][0], sm[(it - 1) & 1][1]);
    }
    cp_wait<0>();
    __syncthreads();
    compute(sm[(iters - 1) & 1][0], sm[(iters - 1) & 1][1]);

    // ---- epilogue
    // EPI==3: band select (each CTA's 128-wide n-range fits one band)
    bf16* Oh = Chi;
    bf16* Ol = Clo;
    const float* bp = bias;
    int nshift = 0;
    if (EPI == 3) {
        const int band = n0 / kH;
        nshift = band * kH;
        if (band == 1) { Oh = Khi; Ol = Klo; bp = bias2; }
        else if (band == 2) { Oh = Vhi; Ol = Vlo; bp = bias3; }
    }

    const size_t zc = (size_t)z * sC;
    #pragma unroll
    for (int mi = 0; mi < 2; mi++) {
        #pragma unroll
        for (int ni = 0; ni < 8; ni++) {
            const int row0 = m0 + wm * 32 + mi * 16 + r;
            const int col  = n0 + wn * 64 + ni * 8 + 2 * q;
            float v0 = acc[mi][ni][0], v1 = acc[mi][ni][1];
            float v2 = acc[mi][ni][2], v3 = acc[mi][ni][3];
            if (EPI == 1 && bias) {
                v0 += bias[col]; v1 += bias[col + 1];
                v2 += bias[col]; v3 += bias[col + 1];
            }
            if (EPI == 2) {
                float b0 = bias[col], b1 = bias[col + 1];
                v0 += b0 + resid[(size_t)row0 * N + col];
                v1 += b1 + resid[(size_t)row0 * N + col + 1];
                v2 += b0 + resid[(size_t)(row0 + 8) * N + col];
                v3 += b1 + resid[(size_t)(row0 + 8) * N + col + 1];
            }
            if (EPI == 3) {
                const int cn = col - nshift;
                float b0 = bp[cn], b1 = bp[cn + 1];
                v0 += b0; v1 += b1; v2 += b0; v3 += b1;
                split2(v0, v1, Oh, Ol, (size_t)row0 * kH + cn);
                split2(v2, v3, Oh, Ol, (size_t)(row0 + 8) * kH + cn);
            } else if (EPI == 0 || EPI == 2) {
                float2 p0 = {v0, v1}, p1 = {v2, v3};
                *(float2*)(Cf + zc + (size_t)row0 * N + col) = p0;
                *(float2*)(Cf + zc + (size_t)(row0 + 8) * N + col) = p1;
            } else {
                split2(v0, v1, Oh, Ol, zc + (size_t)row0 * N + col);
                split2(v2, v3, Oh, Ol, zc + (size_t)(row0 + 8) * N + col);
            }
        }
    }
}

// ---------------------------------------------------------------------------
// fp32 -> bf16 hi/lo elementwise split (x4 vectorized)
// ---------------------------------------------------------------------------
__global__ __launch_bounds__(256)
void split_kernel(const float* __restrict__ x, bf16* __restrict__ hi,
                  bf16* __restrict__ lo, int n4)
{
    int i = blockIdx.x * 256 + threadIdx.x;
    if (i >= n4) return;
    float4 v = *(const float4*)(x + (size_t)i * 4);
    split2(v.x, v.y, hi, lo, (size_t)i * 4);
    split2(v.z, v.w, hi, lo, (size_t)i * 4 + 2);
}

// ---------------------------------------------------------------------------
// W [k][n] fp32  ->  WT hi/lo [n][k] bf16   (768x768), dst at band offset
// ---------------------------------------------------------------------------
__global__ __launch_bounds__(256)
void wsplit_kernel(const float* __restrict__ W, bf16* __restrict__ hi,
                   bf16* __restrict__ lo)
{
    __shared__ float t[32][33];
    const int x = threadIdx.x, y = threadIdx.y;
    const int k0 = blockIdx.y * 32, n0 = blockIdx.x * 32;
    #pragma unroll
    for (int i = 0; i < 4; i++)
        t[y + i * 8][x] = W[(size_t)(k0 + y + i * 8) * kH + n0 + x];
    __syncthreads();
    #pragma unroll
    for (int i = 0; i < 4; i++) {
        float v = t[x][y + i * 8];
        bf16 h = __float2bfloat16(v);
        size_t off = (size_t)(n0 + y + i * 8) * kH + k0 + x;
        hi[off] = h;
        lo[off] = __float2bfloat16(v - __bfloat162float(h));
    }
}

// ---------------------------------------------------------------------------
// V hi/lo [b*2048+t][768]  ->  Vt hi/lo [b][768][2048]
// ---------------------------------------------------------------------------
__global__ __launch_bounds__(256)
void vtrans_kernel(const bf16* __restrict__ vh, const bf16* __restrict__ vl,
                   bf16* __restrict__ oth, bf16* __restrict__ otl)
{
    __shared__ bf16 th[32][33];
    __shared__ bf16 tl[32][33];
    const int x = threadIdx.x, y = threadIdx.y;
    const int t0 = blockIdx.x * 32, h0 = blockIdx.y * 32, z = blockIdx.z;
    #pragma unroll
    for (int i = 0; i < 4; i++) {
        size_t off = (size_t)(z * kS + t0 + y + i * 8) * kH + h0 + x;
        th[y + i * 8][x] = vh[off];
        tl[y + i * 8][x] = vl[off];
    }
    __syncthreads();
    #pragma unroll
    for (int i = 0; i < 4; i++) {
        size_t off = (size_t)z * kH * kS + (size_t)(h0 + y + i * 8) * kS + t0 + x;
        oth[off] = th[x][y + i * 8];
        otl[off] = tl[x][y + i * 8];
    }
}

// ---------------------------------------------------------------------------
// Masked softmax: reads fp32 scores, writes bf16 hi/lo probs. scale fused.
// ---------------------------------------------------------------------------
__global__ __launch_bounds__(256)
void softmax_kernel(const float* __restrict__ P, const int* __restrict__ mask,
                    bf16* __restrict__ phi, bf16* __restrict__ plo)
{
    const int row = blockIdx.x;
    const int b = row >> 11;
    const float* p = P + (size_t)row * kS;
    const int* mrow = mask + (size_t)b * kS;
    const float scale = 0.03608439182435161f;   // 1/sqrt(768)

    float v[8];
    int kp[8];
    float mx = -FLT_MAX;
    #pragma unroll
    for (int i = 0; i < 8; i++) {
        const int t = threadIdx.x + (i << 8);
        kp[i] = mrow[t];
        v[i] = p[t] * scale;
        if (kp[i]) mx = fmaxf(mx, v[i]);
    }
    #pragma unroll
    for (int o = 16; o; o >>= 1) mx = fmaxf(mx, __shfl_xor_sync(~0u, mx, o));
    __shared__ float redm[8];
    if ((threadIdx.x & 31) == 0) redm[threadIdx.x >> 5] = mx;
    __syncthreads();
    float bm = redm[0];
    #pragma unroll
    for (int w = 1; w < 8; w++) bm = fmaxf(bm, redm[w]);

    float sum = 0.f;
    #pragma unroll
    for (int i = 0; i < 8; i++) {
        v[i] = kp[i] ? __expf(v[i] - bm) : 0.f;
        sum += v[i];
    }
    #pragma unroll
    for (int o = 16; o; o >>= 1) sum += __shfl_xor_sync(~0u, sum, o);
    __shared__ float reds[8];
    if ((threadIdx.x & 31) == 0) reds[threadIdx.x >> 5] = sum;
    __syncthreads();
    float bs = 0.f;
    #pragma unroll
    for (int w = 0; w < 8; w++) bs += reds[w];

    const float inv = bs > 0.f ? 1.f / bs : 0.f;
    #pragma unroll
    for (int i = 0; i < 8; i++) {
        const int t = threadIdx.x + (i << 8);
        float pr = v[i] * inv;
        bf16 h = __float2bfloat16(pr);
        size_t off = (size_t)row * kS + t;
        phi[off] = h;
        plo[off] = __float2bfloat16(pr - __bfloat162float(h));
    }
}

// ---------------------------------------------------------------------------
// LayerNorm over last dim (768)
// ---------------------------------------------------------------------------
__global__ __launch_bounds__(256)
void layernorm_kernel(const float* __restrict__ Hin,
                      const float* __restrict__ gamma,
                      const float* __restrict__ beta,
                      float* __restrict__ out)
{
    const int row = blockIdx.x;
    const float* x = Hin + (size_t)row * kH;

    float xv[3];
    float s = 0.f;
    #pragma unroll
    for (int i = 0; i < 3; i++) {
        xv[i] = x[threadIdx.x + i * 256];
        s += xv[i];
    }
    #pragma unroll
    for (int o = 16; o; o >>= 1) s += __shfl_xor_sync(~0u, s, o);
    __shared__ float red1[8];
    if ((threadIdx.x & 31) == 0) red1[threadIdx.x >> 5] = s;
    __syncthreads();
    float tot = 0.f;
    #pragma unroll
    for (int w = 0; w < 8; w++) tot += red1[w];
    const float mu = tot * (1.f / kH);

    float vs = 0.f;
    #pragma unroll
    for (int i = 0; i < 3; i++) {
        const float d = xv[i] - mu;
        vs += d * d;
    }
    #pragma unroll
    for (int o = 16; o; o >>= 1) vs += __shfl_xor_sync(~0u, vs, o);
    __shared__ float red2[8];
    if ((threadIdx.x & 31) == 0) red2[threadIdx.x >> 5] = vs;
    __syncthreads();
    float vtot = 0.f;
    #pragma unroll
    for (int w = 0; w < 8; w++) vtot += red2[w];
    const float inv = rsqrtf(vtot * (1.f / kH) + kEPS);

    #pragma unroll
    for (int i = 0; i < 3; i++) {
        const int c = threadIdx.x + i * 256;
        out[(size_t)row * kH + c] = (xv[i] - mu) * inv * gamma[c] + beta[c];
    }
}

// ---------------------------------------------------------------------------
// Launch
// ---------------------------------------------------------------------------
extern "C" void kernel_launch(void* const* d_in, const int* in_sizes, int n_in,
                              void* d_out, int out_size)
{
    const float* X     = (const float*)d_in[0];
    const int*   mask  = (const int*)  d_in[1];
    const float* Wq    = (const float*)d_in[2];
    const float* bq    = (const float*)d_in[3];
    const float* Wk    = (const float*)d_in[4];
    const float* bk    = (const float*)d_in[5];
    const float* Wv    = (const float*)d_in[6];
    const float* bv    = (const float*)d_in[7];
    const float* Wo    = (const float*)d_in[8];
    const float* bo    = (const float*)d_in[9];
    const float* gamma = (const float*)d_in[10];
    const float* beta  = (const float*)d_in[11];
    float* out = (float*)d_out;

    bf16 *xhi, *xlo, *wqkvth, *wqkvtl, *woth, *wotl;
    bf16 *qhi, *qlo, *khi, *klo, *vhi, *vlo, *vthi, *vtlo;
    bf16 *phi, *plo, *chi, *clo;
    float *pp, *ph;
    cudaGetSymbolAddress((void**)&xhi, g_xhi);     cudaGetSymbolAddress((void**)&xlo, g_xlo);
    cudaGetSymbolAddress((void**)&wqkvth, g_wqkvth);
    cudaGetSymbolAddress((void**)&wqkvtl, g_wqkvtl);
    cudaGetSymbolAddress((void**)&woth, g_woth);   cudaGetSymbolAddress((void**)&wotl, g_wotl);
    cudaGetSymbolAddress((void**)&qhi, g_qhi);     cudaGetSymbolAddress((void**)&qlo, g_qlo);
    cudaGetSymbolAddress((void**)&khi, g_khi);     cudaGetSymbolAddress((void**)&klo, g_klo);
    cudaGetSymbolAddress((void**)&vhi, g_vhi);     cudaGetSymbolAddress((void**)&vlo, g_vlo);
    cudaGetSymbolAddress((void**)&vthi, g_vthi);   cudaGetSymbolAddress((void**)&vtlo, g_vtlo);
    cudaGetSymbolAddress((void**)&phi, g_phi);     cudaGetSymbolAddress((void**)&plo, g_plo);
    cudaGetSymbolAddress((void**)&chi, g_chi);     cudaGetSymbolAddress((void**)&clo, g_clo);
    cudaGetSymbolAddress((void**)&pp, g_p);        cudaGetSymbolAddress((void**)&ph, g_h);

    const dim3 thr(256);
    const size_t wband = (size_t)kH * kH;

    // 0) operand preparation (launches 0-4)
    {
        int n4 = kM * kH / 4;
        split_kernel<<<(n4 + 255) / 256, thr>>>(X, xhi, xlo, n4);
        dim3 wg(kH / 32, kH / 32);
        dim3 wb(32, 8);
        wsplit_kernel<<<wg, wb>>>(Wq, wqkvth, wqkvtl);
        wsplit_kernel<<<wg, wb>>>(Wk, wqkvth + wband, wqkvtl + wband);
        wsplit_kernel<<<wg, wb>>>(Wv, wqkvth + 2 * wband, wqkvtl + 2 * wband);
        wsplit_kernel<<<wg, wb>>>(Wo, woth, wotl);
    }

    // 1) merged QKV projection (launch 5 — profiled by ncu -s 5 -c 1):
    //    [16384, 2304] = X @ [Wq|Wk|Wv]^T, band-selected split bf16 outputs
    {
        dim3 grid(3 * kH / GBN, kM / GBM, 1);
        mma_gemm<3><<<grid, thr>>>(xhi, xlo, wqkvth, wqkvtl,
                                   nullptr, qhi, qlo, bq, nullptr,
                                   kM, 3 * kH, kH, 0, 0, 0,
                                   khi, klo, vhi, vlo, bk, bv);
    }

    // 1b) transpose V -> [b][h][t]
    {
        dim3 g(kS / 32, kH / 32, kB);
        dim3 b(32, 8);
        vtrans_kernel<<<g, b>>>(vhi, vlo, vthi, vtlo);
    }

    // 2) scores[b] = Q[b] @ K[b]^T  (fp32 out)
    {
        dim3 grid(kS / GBN, kS / GBM, kB);
        mma_gemm<0><<<grid, thr>>>(qhi, qlo, khi, klo, pp, nullptr, nullptr,
                                   nullptr, nullptr, kS, kS, kH,
                                   (size_t)kS * kH, (size_t)kS * kH,
                                   (size_t)kS * kS);
    }

    // 3) masked softmax -> split probs
    softmax_kernel<<<kB * kS, thr>>>(pp, mask, phi, plo);

    // 4) ctx[b] = P[b] @ V[b]  (B = Vt [h][t], split out)
    {
        dim3 grid(kH / GBN, kS / GBM, kB);
        mma_gemm<1><<<grid, thr>>>(phi, plo, vthi, vtlo, nullptr, chi, clo,
                                   nullptr, nullptr, kS, kH, kS,
                                   (size_t)kS * kS, (size_t)kH * kS,
                                   (size_t)kS * kH);
    }

    // 5) h = ctx @ Wo^T(pre-transposed) + bo + X
    {
        dim3 grid(kH / GBN, kM / GBM, 1);
        mma_gemm<2><<<grid, thr>>>(chi, clo, woth, wotl, ph, nullptr, nullptr,
                                   bo, X, kM, kH, kH, 0, 0, 0);
    }

    // 6) LayerNorm -> out
    layernorm_kernel<<<kM, thr>>>(ph, gamma, beta, out);
}